// round 1
// baseline (speedup 1.0000x reference)
#include <cuda_runtime.h>
#include <cstdint>

// ---------------------------------------------------------------------------
// PrefilledAttention: B=8, S=2048, D=1024, R=128
//   q = x @ Wq^T   [B,S,128]
//   k = x @ Wk^T   [B,S,128]
//   v = x @ Wv^T   [B,S,1024]
//   scores = q @ k^T / sqrt(128), softmax over t, out = probs @ v
//
// Precision strategy: 3xTF32 (hi/lo split) on q,k,scores (softmax-sensitive),
// plain TF32 on v and probs@v (errors average out). fp32 accumulate everywhere.
// ---------------------------------------------------------------------------

#define BATCH 8
#define SEQ   2048
#define DIM   1024
#define RANK  128

#define BM 128
#define BN 128
#define BK 32
#define NTHREADS 256

// Scratch (allocation-free rule: __device__ globals)
__device__ float g_q[(size_t)BATCH * SEQ * RANK];                 // 8 MB
__device__ float g_k[(size_t)BATCH * SEQ * RANK];                 // 8 MB
__device__ float g_v[(size_t)BATCH * SEQ * DIM];                  // 64 MB
__device__ float g_s[(size_t)BATCH * SEQ * SEQ];                  // 128 MB

// ---------------------------------------------------------------------------
// helpers
// ---------------------------------------------------------------------------
__device__ __forceinline__ uint32_t tf32_of(float v) {
    uint32_t r;
    asm("cvt.rna.tf32.f32 %0, %1;" : "=r"(r) : "f"(v));
    return r;
}

__device__ __forceinline__ void cp_async16(void* smem, const void* gmem) {
    uint32_t s = (uint32_t)__cvta_generic_to_shared(smem);
    asm volatile("cp.async.cg.shared.global [%0], [%1], 16;\n" :: "r"(s), "l"(gmem));
}
__device__ __forceinline__ void cp_commit() {
    asm volatile("cp.async.commit_group;\n");
}
template <int N>
__device__ __forceinline__ void cp_wait() {
    asm volatile("cp.async.wait_group %0;\n" :: "n"(N));
}

__device__ __forceinline__ void mma_tf32(float* c, const uint32_t* a, const uint32_t* b) {
    asm volatile(
        "mma.sync.aligned.m16n8k8.row.col.f32.tf32.tf32.f32 "
        "{%0,%1,%2,%3}, {%4,%5,%6,%7}, {%8,%9}, {%0,%1,%2,%3};"
        : "+f"(c[0]), "+f"(c[1]), "+f"(c[2]), "+f"(c[3])
        : "r"(a[0]), "r"(a[1]), "r"(a[2]), "r"(a[3]), "r"(b[0]), "r"(b[1]));
}

// ---------------------------------------------------------------------------
// Tiled GEMM:  C[M,N] = alpha * A[M,K] * op(B)
//   BKMAJ=true : B is [N,K] row-major (K contiguous), computes A*B^T
//   BKMAJ=false: B is [K,N] row-major (N contiguous), computes A*B
//   X3=true    : 3xTF32 (near-fp32 precision); false: single tf32 pass
// All dims must be multiples of 128 (M,N) and 32 (K) — true for every call.
// blockIdx.z = batch; per-batch strides aS,bS,cS (0 for shared weights).
// ---------------------------------------------------------------------------
template <bool BKMAJ, bool X3>
__global__ void __launch_bounds__(NTHREADS)
gemm_kernel(const float* __restrict__ A, const float* __restrict__ Bm,
            float* __restrict__ C, int M, int N, int K,
            long aS, long bS, long cS, float alpha)
{
    constexpr int SA  = 36;                     // padded A smem stride (floats)
    constexpr int SB  = BKMAJ ? 36 : 136;       // padded B smem stride
    constexpr int ASZ = 128 * SA;
    constexpr int BSZ = BKMAJ ? 128 * 36 : 32 * 136;
    constexpr int STAGE = ASZ + BSZ;

    extern __shared__ float sm[];

    const float* Ab = A  + (long)blockIdx.z * aS;
    const float* Bb = Bm + (long)blockIdx.z * bS;
    float*       Cb = C  + (long)blockIdx.z * cS;

    const int bm = blockIdx.y * BM;
    const int bn = blockIdx.x * BN;
    const int tid = threadIdx.x;

    // ---- tile loaders (cp.async, 16B) ----
    const int arow = tid >> 3;            // 0..31
    const int ac4  = (tid & 7) * 4;       // float offset, 16B granularity
    int brow, bc4;
    if (BKMAJ) { brow = tid >> 3; bc4 = (tid & 7) * 4; }
    else       { brow = tid >> 5; bc4 = (tid & 31) * 4; }

    auto load_tile = [&](int kt, int stage) {
        float* As = sm + stage * STAGE;
        float* Bs = As + ASZ;
        const float* Ag = Ab + (size_t)bm * K + kt * BK;
#pragma unroll
        for (int i = 0; i < 4; i++) {
            int r = arow + i * 32;
            cp_async16(&As[r * SA + ac4], Ag + (size_t)r * K + ac4);
        }
        if (BKMAJ) {
            const float* Bg = Bb + (size_t)bn * K + kt * BK;
#pragma unroll
            for (int i = 0; i < 4; i++) {
                int r = brow + i * 32;
                cp_async16(&Bs[r * SB + bc4], Bg + (size_t)r * K + bc4);
            }
        } else {
            const float* Bg = Bb + (size_t)(kt * BK) * N + bn;
#pragma unroll
            for (int i = 0; i < 4; i++) {
                int r = brow + i * 8;
                cp_async16(&Bs[r * SB + bc4], Bg + (size_t)r * N + bc4);
            }
        }
    };

    // ---- warp/fragment indexing ----
    const int lane = tid & 31;
    const int warp = tid >> 5;
    const int wm = warp & 1;          // 2 warps along M
    const int wn = warp >> 1;         // 4 warps along N
    const int g  = lane >> 2;         // groupID   0..7
    const int tg = lane & 3;          // thread-in-group 0..3

    float acc[4][4][4];
#pragma unroll
    for (int a = 0; a < 4; a++)
#pragma unroll
        for (int b = 0; b < 4; b++)
#pragma unroll
            for (int c = 0; c < 4; c++) acc[a][b][c] = 0.f;

    const int KT = K / BK;
    load_tile(0, 0);
    cp_commit();

    for (int kt = 0; kt < KT; kt++) {
        if (kt + 1 < KT) {
            load_tile(kt + 1, (kt + 1) & 1);
            cp_commit();
            cp_wait<1>();
        } else {
            cp_wait<0>();
        }
        __syncthreads();

        const float* As = sm + (kt & 1) * STAGE;
        const float* Bs = As + ASZ;

#pragma unroll
        for (int ks = 0; ks < 4; ks++) {
            const int kk = ks * 8;

            uint32_t ahi[4][4], alo[4][4];
#pragma unroll
            for (int mf = 0; mf < 4; mf++) {
                int r0 = wm * 64 + mf * 16 + g;
                float v0 = As[r0 * SA + kk + tg];
                float v1 = As[(r0 + 8) * SA + kk + tg];
                float v2 = As[r0 * SA + kk + tg + 4];
                float v3 = As[(r0 + 8) * SA + kk + tg + 4];
                ahi[mf][0] = tf32_of(v0);
                ahi[mf][1] = tf32_of(v1);
                ahi[mf][2] = tf32_of(v2);
                ahi[mf][3] = tf32_of(v3);
                if (X3) {
                    alo[mf][0] = tf32_of(v0 - __uint_as_float(ahi[mf][0]));
                    alo[mf][1] = tf32_of(v1 - __uint_as_float(ahi[mf][1]));
                    alo[mf][2] = tf32_of(v2 - __uint_as_float(ahi[mf][2]));
                    alo[mf][3] = tf32_of(v3 - __uint_as_float(ahi[mf][3]));
                }
            }

            uint32_t bhi[4][2], blo[4][2];
#pragma unroll
            for (int nf = 0; nf < 4; nf++) {
                int n = wn * 32 + nf * 8 + g;
                float v0, v1;
                if (BKMAJ) {
                    v0 = Bs[n * SB + kk + tg];
                    v1 = Bs[n * SB + kk + tg + 4];
                } else {
                    v0 = Bs[(kk + tg) * SB + n];
                    v1 = Bs[(kk + tg + 4) * SB + n];
                }
                bhi[nf][0] = tf32_of(v0);
                bhi[nf][1] = tf32_of(v1);
                if (X3) {
                    blo[nf][0] = tf32_of(v0 - __uint_as_float(bhi[nf][0]));
                    blo[nf][1] = tf32_of(v1 - __uint_as_float(bhi[nf][1]));
                }
            }

#pragma unroll
            for (int mf = 0; mf < 4; mf++)
#pragma unroll
                for (int nf = 0; nf < 4; nf++) {
                    if (X3) {
                        mma_tf32(acc[mf][nf], alo[mf], bhi[nf]);
                        mma_tf32(acc[mf][nf], ahi[mf], blo[nf]);
                    }
                    mma_tf32(acc[mf][nf], ahi[mf], bhi[nf]);
                }
        }
        __syncthreads();
    }

    // ---- epilogue ----
#pragma unroll
    for (int mf = 0; mf < 4; mf++) {
        int r0 = bm + wm * 64 + mf * 16 + g;
#pragma unroll
        for (int nf = 0; nf < 4; nf++) {
            int c0 = bn + wn * 32 + nf * 8 + tg * 2;
            float2 t0 = make_float2(acc[mf][nf][0] * alpha, acc[mf][nf][1] * alpha);
            float2 t1 = make_float2(acc[mf][nf][2] * alpha, acc[mf][nf][3] * alpha);
            *(float2*)(Cb + (size_t)r0 * N + c0)       = t0;
            *(float2*)(Cb + (size_t)(r0 + 8) * N + c0) = t1;
        }
    }
}

// ---------------------------------------------------------------------------
// Row softmax, in place. One CTA per row of 2048 floats, 256 threads x 8 vals.
// ---------------------------------------------------------------------------
__global__ void __launch_bounds__(256) softmax_kernel(float* __restrict__ S)
{
    float4* row = (float4*)(S + (size_t)blockIdx.x * SEQ);
    const int tid = threadIdx.x;

    float4 a = row[tid];
    float4 b = row[tid + 256];

    float m = fmaxf(fmaxf(fmaxf(a.x, a.y), fmaxf(a.z, a.w)),
                    fmaxf(fmaxf(b.x, b.y), fmaxf(b.z, b.w)));

    __shared__ float red[8];
#pragma unroll
    for (int o = 16; o; o >>= 1) m = fmaxf(m, __shfl_xor_sync(0xffffffffu, m, o));
    if ((tid & 31) == 0) red[tid >> 5] = m;
    __syncthreads();
    m = red[0];
#pragma unroll
    for (int i = 1; i < 8; i++) m = fmaxf(m, red[i]);
    __syncthreads();

    a.x = __expf(a.x - m); a.y = __expf(a.y - m);
    a.z = __expf(a.z - m); a.w = __expf(a.w - m);
    b.x = __expf(b.x - m); b.y = __expf(b.y - m);
    b.z = __expf(b.z - m); b.w = __expf(b.w - m);

    float s = a.x + a.y + a.z + a.w + b.x + b.y + b.z + b.w;
#pragma unroll
    for (int o = 16; o; o >>= 1) s += __shfl_xor_sync(0xffffffffu, s, o);
    if ((tid & 31) == 0) red[tid >> 5] = s;
    __syncthreads();
    float tot = red[0];
#pragma unroll
    for (int i = 1; i < 8; i++) tot += red[i];

    float inv = 1.0f / tot;
    a.x *= inv; a.y *= inv; a.z *= inv; a.w *= inv;
    b.x *= inv; b.y *= inv; b.z *= inv; b.w *= inv;

    row[tid]       = a;
    row[tid + 256] = b;
}

// ---------------------------------------------------------------------------
// launch
// ---------------------------------------------------------------------------
extern "C" void kernel_launch(void* const* d_in, const int* in_sizes, int n_in,
                              void* d_out, int out_size)
{
    (void)in_sizes; (void)n_in; (void)out_size;
    const float* x  = (const float*)d_in[0];
    const float* Wq = (const float*)d_in[1];
    const float* Wk = (const float*)d_in[2];
    const float* Wv = (const float*)d_in[3];
    float* out = (float*)d_out;

    void *pq, *pk, *pv, *ps;
    cudaGetSymbolAddress(&pq, g_q);
    cudaGetSymbolAddress(&pk, g_k);
    cudaGetSymbolAddress(&pv, g_v);
    cudaGetSymbolAddress(&ps, g_s);
    float* q = (float*)pq;
    float* k = (float*)pk;
    float* v = (float*)pv;
    float* s = (float*)ps;

    const int SMEM_T = (128 * 36 + 128 * 36) * 2 * 4;   // 73728 B (BKMAJ tiles)
    const int SMEM_N = (128 * 36 + 32 * 136) * 2 * 4;   // 71680 B (N-major B)

    cudaFuncSetAttribute((const void*)gemm_kernel<true,  true >,
                         cudaFuncAttributeMaxDynamicSharedMemorySize, SMEM_T);
    cudaFuncSetAttribute((const void*)gemm_kernel<true,  false>,
                         cudaFuncAttributeMaxDynamicSharedMemorySize, SMEM_T);
    cudaFuncSetAttribute((const void*)gemm_kernel<false, false>,
                         cudaFuncAttributeMaxDynamicSharedMemorySize, SMEM_N);

    const int MT = BATCH * SEQ;              // 16384 flattened tokens
    const float scale = 0.08838834764831845f; // 1/sqrt(128)

    // q = x @ Wq^T   (3xTF32)
    gemm_kernel<true, true><<<dim3(RANK / BN, MT / BM, 1), NTHREADS, SMEM_T>>>(
        x, Wq, q, MT, RANK, DIM, 0, 0, 0, 1.f);
    // k = x @ Wk^T   (3xTF32)
    gemm_kernel<true, true><<<dim3(RANK / BN, MT / BM, 1), NTHREADS, SMEM_T>>>(
        x, Wk, k, MT, RANK, DIM, 0, 0, 0, 1.f);
    // v = x @ Wv^T   (tf32)
    gemm_kernel<true, false><<<dim3(DIM / BN, MT / BM, 1), NTHREADS, SMEM_T>>>(
        x, Wv, v, MT, DIM, DIM, 0, 0, 0, 1.f);
    // scores = q @ k^T * scale   (3xTF32, batched)
    gemm_kernel<true, true><<<dim3(SEQ / BN, SEQ / BM, BATCH), NTHREADS, SMEM_T>>>(
        q, k, s, SEQ, SEQ, RANK,
        (long)SEQ * RANK, (long)SEQ * RANK, (long)SEQ * SEQ, scale);
    // softmax rows (in place)
    softmax_kernel<<<BATCH * SEQ, 256>>>(s);
    // out = probs @ v   (tf32, batched, B is N-major)
    gemm_kernel<false, false><<<dim3(DIM / BN, SEQ / BM, BATCH), NTHREADS, SMEM_N>>>(
        s, v, out, SEQ, DIM, SEQ,
        (long)SEQ * SEQ, (long)SEQ * DIM, (long)SEQ * DIM, 1.f);
}